// round 15
// baseline (speedup 1.0000x reference)
#include <cuda_runtime.h>
#include <cuda_bf16.h>
#include <cstdint>

// ============================================================================
// Mean-field CRF on GB300 (plain sm_103 PTX; mma.sync m16n8k16 bf16).
// K_sp/K_bl symmetric, stored FRAGMENT-BLOCKED per 256x256 block pair (p<=q).
// k_gemm: barrier-free, smem-free; forward B-frags via direct LDG.128, mirror
// B-frags via movmatrix in-register transpose; results via red.global atomics
// into zero-invariant g_red. Grid = 4 quarter-units per pair (2 chunks each)
// -> 2112 CTAs, ~99% wave-slot efficiency (vs 87% at 528).
//   q = unaries + (A_sp p) K_sp + (A_bl p) K_bl,  A_* = -(compat @ W_*)
// ============================================================================

#define DI __device__ __forceinline__

static constexpr int   NPT   = 8192;
static constexpr int   NC    = 10;
static constexpr int   CP    = 16;
static constexpr int   NBLK  = 32;                       // 256-point blocks
static constexpr int   NPAIR = NBLK * (NBLK + 1) / 2;    // 528
static constexpr int   BLKU4 = 8192;                     // uint4 per block pair
static constexpr float LOG2E = 1.4426950408889634f;
static constexpr float ESP   = LOG2E / 64.0f;
static constexpr float EBL   = LOG2E;

// ---- static device scratch --------------------------------------------------
__device__ __align__(1024) __nv_bfloat16 g_Ksp[(size_t)NPAIR * BLKU4 * 8]; // 69 MB
__device__ __align__(1024) __nv_bfloat16 g_Kbl[(size_t)NPAIR * BLKU4 * 8]; // 69 MB
__device__ __align__(1024) uint4 g_PF[2][512][32];   // A-fragments per k16 step
__device__ __align__(256)  float g_red[NC * NPT];    // pairwise accumulator
                                                     // invariant: zero between launches

DI float ex2f(float x) { float y; asm("ex2.approx.f32 %0, %1;" : "=f"(y) : "f"(x)); return y; }
DI void redg2(float* a, float x, float y) {
    asm volatile("red.global.add.v2.f32 [%0], {%1, %2};" :: "l"(a), "f"(x), "f"(y) : "memory");
}
DI void mma16816(float* c, const uint32_t* a, uint32_t b0, uint32_t b1) {
    asm volatile(
        "mma.sync.aligned.m16n8k16.row.col.f32.bf16.bf16.f32 "
        "{%0,%1,%2,%3}, {%4,%5,%6,%7}, {%8,%9}, {%0,%1,%2,%3};"
        : "+f"(c[0]), "+f"(c[1]), "+f"(c[2]), "+f"(c[3])
        : "r"(a[0]), "r"(a[1]), "r"(a[2]), "r"(a[3]), "r"(b0), "r"(b1));
}
DI uint32_t movm(uint32_t a) {
    uint32_t d;
    asm volatile("movmatrix.sync.aligned.m8n8.trans.b16 %0, %1;" : "=r"(d) : "r"(a));
    return d;
}
DI int pair_rank(int p, int q) { return p * (2 * NBLK - p + 1) / 2 + (q - p); }

// ---------------- ncu index shim (launch 0) ----------------------------------
__global__ void k_nop() {}

// ---------------- kernel builder: fragment-blocked pair storage --------------
__global__ __launch_bounds__(256) void k_pairs(const float* __restrict__ feat) {
    int bi = blockIdx.y, bj = blockIdx.x;
    if (!(bj >= bi || (bj == bi - 1 && (bi & 1)))) return;

    __shared__ float sfi[6][128], sfj[6][128], shs[128], shb[128];
    int t = threadIdx.x;
    int i0 = bi * 128, j0 = bj * 128;

    for (int v = t; v < 6 * 128; v += 256) {
        int d = v >> 7, x = v & 127;
        sfi[d][x] = feat[d * NPT + i0 + x];
        sfj[d][x] = feat[d * NPT + j0 + x];
    }
    __syncthreads();
    if (t < 128) {
        float n3 = sfi[0][t] * sfi[0][t] + sfi[1][t] * sfi[1][t] + sfi[2][t] * sfi[2][t];
        float n6 = n3 + sfi[3][t] * sfi[3][t] + sfi[4][t] * sfi[4][t] + sfi[5][t] * sfi[5][t];
        shs[t] = 0.5f * ESP * n3;
        shb[t] = 0.5f * EBL * n6;
    }
    __syncthreads();

    int w = t >> 5, lane = t & 31;
    int ir = lane >> 2, tq = lane & 3;
    int js_local = w & 3;
    int itgrp    = w >> 2;

    int jl[8];
#pragma unroll
    for (int u = 0; u < 8; u++)
        jl[u] = js_local * 32 + tq * 2 + (u & 1) + ((u >> 1) << 3);

    float fj[6][8], hsj[8], hbj[8];
#pragma unroll
    for (int d = 0; d < 6; d++)
#pragma unroll
        for (int u = 0; u < 8; u++) fj[d][u] = sfj[d][jl[u]];
#pragma unroll
    for (int u = 0; u < 8; u++) {
        float n3 = fj[0][u] * fj[0][u] + fj[1][u] * fj[1][u] + fj[2][u] * fj[2][u];
        float n6 = n3 + fj[3][u] * fj[3][u] + fj[4][u] * fj[4][u] + fj[5][u] * fj[5][u];
        hsj[u] = 0.5f * ESP * n3;
        hbj[u] = 0.5f * EBL * n6;
    }

    int P = bi >> 1, Q = bj >> 1;
    size_t base4 = (size_t)pair_rank(P, Q) * BLKU4;
    int js_blk = (bj & 1) * 4 + js_local;

#pragma unroll 1
    for (int r = 0; r < 8; r++) {
        int it_local = r * 2 + itgrp;
        int il = it_local * 8 + ir;
        float f0 = sfi[0][il], f1 = sfi[1][il], f2 = sfi[2][il];
        float f3 = sfi[3][il], f4 = sfi[4][il], f5 = sfi[5][il];
        float hs = shs[il], hb = shb[il];

        uint32_t ps[4], pb[4];
#pragma unroll
        for (int g2 = 0; g2 < 4; g2++) {
            float vs[2], vb[2];
#pragma unroll
            for (int u2 = 0; u2 < 2; u2++) {
                int u = g2 * 2 + u2;
                float d3 = fmaf(f2, fj[2][u], fmaf(f1, fj[1][u], f0 * fj[0][u]));
                float dh = fmaf(f5, fj[5][u], fmaf(f4, fj[4][u], f3 * fj[3][u]));
                float d6 = d3 + dh;
                vs[u2] = ex2f(fmaf(ESP, d3, -(hs + hsj[u])));
                vb[u2] = ex2f(fmaf(EBL, d6, -(hb + hbj[u])));
            }
            __nv_bfloat162 s2 = __floats2bfloat162_rn(vs[0], vs[1]);
            __nv_bfloat162 b2 = __floats2bfloat162_rn(vb[0], vb[1]);
            ps[g2] = *reinterpret_cast<uint32_t*>(&s2);
            pb[g2] = *reinterpret_cast<uint32_t*>(&b2);
        }
        int it_blk = (bi & 1) * 16 + it_local;
        size_t u4 = base4 + ((size_t)it_blk * 8 + js_blk) * 32 + lane;
        reinterpret_cast<uint4*>(g_Ksp)[u4] = make_uint4(ps[0], ps[1], ps[2], ps[3]);
        reinterpret_cast<uint4*>(g_Kbl)[u4] = make_uint4(pb[0], pb[1], pb[2], pb[3]);
    }
}

// ---------------- softmax + P-fragment writer / final output -----------------
// mode 0: q = unaries -> PF
// mode 1: q = unaries + g_red -> PF   (then zero g_red)
// mode 2: q = unaries + g_red -> out  (then zero g_red)
__global__ __launch_bounds__(128) void k_soft(const float* __restrict__ unaries,
                                              const float* __restrict__ Wsp,
                                              const float* __restrict__ Wbl,
                                              const float* __restrict__ Comp,
                                              float* __restrict__ out,
                                              int mode) {
    __shared__ float sW1[NC * NC], sW2[NC * NC];
    int tl = threadIdx.x;
    int j = blockIdx.x * 128 + tl;

    if (mode != 2 && tl < NC * NC) {
        int c = tl / NC, c2 = tl % NC;
        float s1 = 0.f, s2 = 0.f;
#pragma unroll
        for (int k = 0; k < NC; k++) {
            s1 += Comp[c * NC + k] * Wsp[k * NC + c2];
            s2 += Comp[c * NC + k] * Wbl[k * NC + c2];
        }
        sW1[tl] = -s1;
        sW2[tl] = -s2;
    }
    if (mode != 2) __syncthreads();

    float q[NC];
#pragma unroll
    for (int c = 0; c < NC; c++) q[c] = unaries[(size_t)c * NPT + j];
    if (mode) {
#pragma unroll
        for (int c = 0; c < NC; c++) {
            q[c] += g_red[c * NPT + j];
            g_red[c * NPT + j] = 0.f;      // restore zero invariant
        }
    }
    if (mode == 2) {
#pragma unroll
        for (int c = 0; c < NC; c++) out[(size_t)c * NPT + j] = q[c];
        return;
    }
    float p[NC];
    float m = q[0];
#pragma unroll
    for (int c = 1; c < NC; c++) m = fmaxf(m, q[c]);
    float s = 0.f;
#pragma unroll
    for (int c = 0; c < NC; c++) { p[c] = ex2f((q[c] - m) * LOG2E); s += p[c]; }
    float inv = __fdividef(1.f, s);
#pragma unroll
    for (int c = 0; c < NC; c++) p[c] *= inv;

    int T  = j >> 1, u = j & 1;
    int ks = T >> 3, tq = T & 3;
    int hik = ((T & 7) >= 4) ? 2 : 0;
#pragma unroll
    for (int c16 = 0; c16 < CP; c16++) {
        float v1 = 0.f, v2 = 0.f;
        if (c16 < NC) {
#pragma unroll
            for (int c = 0; c < NC; c++) {
                v1 = fmaf(sW1[c16 * NC + c], p[c], v1);
                v2 = fmaf(sW2[c16 * NC + c], p[c], v2);
            }
        }
        int lane = (c16 & 7) * 4 + tq;
        int reg  = ((c16 >= 8) ? 1 : 0) + hik;
        reinterpret_cast<__nv_bfloat16*>(&g_PF[0][ks][lane])[reg * 2 + u] =
            __float2bfloat16(v1);
        reinterpret_cast<__nv_bfloat16*>(&g_PF[1][ks][lane])[reg * 2 + u] =
            __float2bfloat16(v2);
    }
}

// ---------------- symmetric GEMM: barrier-free, quarter-pair units -----------
// CTA = (pair, quarter h): chunks 2h, 2h+1. Forward: direct-LDG B-frags;
// mirror: movmatrix transpose of the same regs. All results via red.global.
__global__ __launch_bounds__(256, 2) void k_gemm() {
    int t = threadIdx.x, w = t >> 5, lane = t & 31, g = lane >> 2, tq = lane & 3;

    int pr = blockIdx.x >> 2;
    int h  = blockIdx.x & 3;
    int idx = pr, p = 0;
    while (idx >= NBLK - p) { idx -= NBLK - p; p++; }
    int q = p + idx;
    bool diag = (p == q);

    const uint4* K1 = reinterpret_cast<const uint4*>(g_Ksp) + (size_t)pr * BLKU4;
    const uint4* K2 = reinterpret_cast<const uint4*>(g_Kbl) + (size_t)pr * BLKU4;

    // mirror A-fragments: constant across chunks (k16 groups w*2, w*2+1 of p)
    uint4 MA1[2], MA2[2];
#pragma unroll
    for (int s = 0; s < 2; s++) {
        MA1[s] = g_PF[0][p * 16 + w * 2 + s][lane];
        MA2[s] = g_PF[1][p * 16 + w * 2 + s][lane];
    }

    float facc[4][4] = {};

#pragma unroll
    for (int cc = 0; cc < 2; cc++) {
        int cs = h * 2 + cc;
        // forward A-fragments for this chunk's 32 j (two k16 steps)
        int ks0 = q * 16 + cs * 2;
        uint4 A1a = g_PF[0][ks0][lane], A1b = g_PF[0][ks0 + 1][lane];
        uint4 A2a = g_PF[1][ks0][lane], A2b = g_PF[1][ks0 + 1][lane];

        // front-batched B loads: 8 contiguous 512B LDG.128 per warp
        uint4 B1[4], B2[4];
#pragma unroll
        for (int tt = 0; tt < 4; tt++) {
            size_t u4 = ((size_t)(w * 4 + tt) * 8 + cs) * 32 + lane;
            B1[tt] = K1[u4];
            B2[tt] = K2[u4];
        }

        // ---- forward: out[i in p-block] += P(q) . K ----
#pragma unroll
        for (int tt = 0; tt < 4; tt++) {
            mma16816(facc[tt], reinterpret_cast<const uint32_t*>(&A1a), B1[tt].x, B1[tt].y);
            mma16816(facc[tt], reinterpret_cast<const uint32_t*>(&A1b), B1[tt].z, B1[tt].w);
            mma16816(facc[tt], reinterpret_cast<const uint32_t*>(&A2a), B2[tt].x, B2[tt].y);
            mma16816(facc[tt], reinterpret_cast<const uint32_t*>(&A2b), B2[tt].z, B2[tt].w);
        }

        // ---- mirror: out[j in q-block] += P(p) . K^T (movmatrix transpose) --
        if (!diag) {
            uint32_t T1[4][4], T2[4][4];
#pragma unroll
            for (int tt = 0; tt < 4; tt++) {
                const uint32_t* b1 = reinterpret_cast<const uint32_t*>(&B1[tt]);
                const uint32_t* b2 = reinterpret_cast<const uint32_t*>(&B2[tt]);
#pragma unroll
                for (int jo = 0; jo < 4; jo++) {
                    T1[tt][jo] = movm(b1[jo]);
                    T2[tt][jo] = movm(b2[jo]);
                }
            }
#pragma unroll
            for (int jo = 0; jo < 4; jo++) {
                float macc[4] = {0.f, 0.f, 0.f, 0.f};
                mma16816(macc, reinterpret_cast<const uint32_t*>(&MA1[0]), T1[0][jo], T1[1][jo]);
                mma16816(macc, reinterpret_cast<const uint32_t*>(&MA1[1]), T1[2][jo], T1[3][jo]);
                mma16816(macc, reinterpret_cast<const uint32_t*>(&MA2[0]), T2[0][jo], T2[1][jo]);
                mma16816(macc, reinterpret_cast<const uint32_t*>(&MA2[1]), T2[2][jo], T2[3][jo]);
                int j = q * 256 + cs * 32 + jo * 8 + tq * 2;
                redg2(&g_red[g * NPT + j], macc[0], macc[1]);
                if (g < NC - 8)
                    redg2(&g_red[(g + 8) * NPT + j], macc[2], macc[3]);
            }
        }
    }

    // ---- forward epilogue (per quarter-unit) ----
#pragma unroll
    for (int tt = 0; tt < 4; tt++) {
        int i = p * 256 + (w * 4 + tt) * 8 + tq * 2;
        redg2(&g_red[g * NPT + i], facc[tt][0], facc[tt][1]);
        if (g < NC - 8)
            redg2(&g_red[(g + 8) * NPT + i], facc[tt][2], facc[tt][3]);
    }
}

// ---------------- launch ------------------------------------------------------
extern "C" void kernel_launch(void* const* d_in, const int* in_sizes, int n_in,
                              void* d_out, int out_size) {
    const float* unaries = (const float*)d_in[0];
    const float* feat    = (const float*)d_in[1];
    const float* Wsp     = (const float*)d_in[2];
    const float* Wbl     = (const float*)d_in[3];
    const float* Comp    = (const float*)d_in[4];
    float* out = (float*)d_out;

    k_nop<<<1, 32>>>();                                           // 0 (ncu shim)
    k_pairs<<<dim3(64, 64), 256>>>(feat);                         // 1
    k_soft<<<NPT / 128, 128>>>(unaries, Wsp, Wbl, Comp, out, 0);  // 2
    for (int it = 0; it < 5; it++) {
        k_gemm<<<NPAIR * 4, 256>>>();                             // 3,5,7,9,11 (5 = iter1)
        k_soft<<<NPT / 128, 128>>>(unaries, Wsp, Wbl, Comp, out,
                                   (it == 4) ? 2 : 1);            // 4,6,8,10,12
    }
}

// round 17
// speedup vs baseline: 1.1000x; 1.1000x over previous
#include <cuda_runtime.h>
#include <cuda_bf16.h>
#include <cstdint>

// ============================================================================
// Mean-field CRF on GB300 (plain sm_103 PTX; mma.sync m16n8k16 bf16).
// K_sp/K_bl symmetric, stored FRAGMENT-BLOCKED per 256x256 block pair (p<=q).
// k_gemm (R13-verified): barrier-free, smem-free, 528 pair-CTAs; forward
// B-frags via direct LDG.128, mirror B-frags via movmatrix in-register
// transpose; + L2 prefetch of next chunk. Results via red.global atomics into
// zero-invariant g_red (k_soft reads + rezeroes).
//   q = unaries + (A_sp p) K_sp + (A_bl p) K_bl,  A_* = -(compat @ W_*)
// ============================================================================

#define DI __device__ __forceinline__

static constexpr int   NPT   = 8192;
static constexpr int   NC    = 10;
static constexpr int   CP    = 16;
static constexpr int   NBLK  = 32;                       // 256-point blocks
static constexpr int   NPAIR = NBLK * (NBLK + 1) / 2;    // 528
static constexpr int   BLKU4 = 8192;                     // uint4 per block pair
static constexpr float LOG2E = 1.4426950408889634f;
static constexpr float ESP   = LOG2E / 64.0f;
static constexpr float EBL   = LOG2E;

// ---- static device scratch --------------------------------------------------
__device__ __align__(1024) __nv_bfloat16 g_Ksp[(size_t)NPAIR * BLKU4 * 8]; // 69 MB
__device__ __align__(1024) __nv_bfloat16 g_Kbl[(size_t)NPAIR * BLKU4 * 8]; // 69 MB
__device__ __align__(1024) uint4 g_PF[2][512][32];   // A-fragments per k16 step
__device__ __align__(256)  float g_red[NC * NPT];    // pairwise accumulator
                                                     // invariant: zero between launches

DI float ex2f(float x) { float y; asm("ex2.approx.f32 %0, %1;" : "=f"(y) : "f"(x)); return y; }
DI void redg2(float* a, float x, float y) {
    asm volatile("red.global.add.v2.f32 [%0], {%1, %2};" :: "l"(a), "f"(x), "f"(y) : "memory");
}
DI void pf_l2(const void* g) {
    asm volatile("prefetch.global.L2 [%0];" :: "l"(g));
}
DI void mma16816(float* c, const uint32_t* a, uint32_t b0, uint32_t b1) {
    asm volatile(
        "mma.sync.aligned.m16n8k16.row.col.f32.bf16.bf16.f32 "
        "{%0,%1,%2,%3}, {%4,%5,%6,%7}, {%8,%9}, {%0,%1,%2,%3};"
        : "+f"(c[0]), "+f"(c[1]), "+f"(c[2]), "+f"(c[3])
        : "r"(a[0]), "r"(a[1]), "r"(a[2]), "r"(a[3]), "r"(b0), "r"(b1));
}
DI uint32_t movm(uint32_t a) {
    uint32_t d;
    asm volatile("movmatrix.sync.aligned.m8n8.trans.b16 %0, %1;" : "=r"(d) : "r"(a));
    return d;
}
DI int pair_rank(int p, int q) { return p * (2 * NBLK - p + 1) / 2 + (q - p); }

// ---------------- ncu index shim (launch 0) ----------------------------------
__global__ void k_nop() {}

// ---------------- kernel builder: fragment-blocked pair storage --------------
__global__ __launch_bounds__(256) void k_pairs(const float* __restrict__ feat) {
    int bi = blockIdx.y, bj = blockIdx.x;
    if (!(bj >= bi || (bj == bi - 1 && (bi & 1)))) return;

    __shared__ float sfi[6][128], sfj[6][128], shs[128], shb[128];
    int t = threadIdx.x;
    int i0 = bi * 128, j0 = bj * 128;

    for (int v = t; v < 6 * 128; v += 256) {
        int d = v >> 7, x = v & 127;
        sfi[d][x] = feat[d * NPT + i0 + x];
        sfj[d][x] = feat[d * NPT + j0 + x];
    }
    __syncthreads();
    if (t < 128) {
        float n3 = sfi[0][t] * sfi[0][t] + sfi[1][t] * sfi[1][t] + sfi[2][t] * sfi[2][t];
        float n6 = n3 + sfi[3][t] * sfi[3][t] + sfi[4][t] * sfi[4][t] + sfi[5][t] * sfi[5][t];
        shs[t] = 0.5f * ESP * n3;
        shb[t] = 0.5f * EBL * n6;
    }
    __syncthreads();

    int w = t >> 5, lane = t & 31;
    int ir = lane >> 2, tq = lane & 3;
    int js_local = w & 3;
    int itgrp    = w >> 2;

    int jl[8];
#pragma unroll
    for (int u = 0; u < 8; u++)
        jl[u] = js_local * 32 + tq * 2 + (u & 1) + ((u >> 1) << 3);

    float fj[6][8], hsj[8], hbj[8];
#pragma unroll
    for (int d = 0; d < 6; d++)
#pragma unroll
        for (int u = 0; u < 8; u++) fj[d][u] = sfj[d][jl[u]];
#pragma unroll
    for (int u = 0; u < 8; u++) {
        float n3 = fj[0][u] * fj[0][u] + fj[1][u] * fj[1][u] + fj[2][u] * fj[2][u];
        float n6 = n3 + fj[3][u] * fj[3][u] + fj[4][u] * fj[4][u] + fj[5][u] * fj[5][u];
        hsj[u] = 0.5f * ESP * n3;
        hbj[u] = 0.5f * EBL * n6;
    }

    int P = bi >> 1, Q = bj >> 1;
    size_t base4 = (size_t)pair_rank(P, Q) * BLKU4;
    int js_blk = (bj & 1) * 4 + js_local;

#pragma unroll 1
    for (int r = 0; r < 8; r++) {
        int it_local = r * 2 + itgrp;
        int il = it_local * 8 + ir;
        float f0 = sfi[0][il], f1 = sfi[1][il], f2 = sfi[2][il];
        float f3 = sfi[3][il], f4 = sfi[4][il], f5 = sfi[5][il];
        float hs = shs[il], hb = shb[il];

        uint32_t ps[4], pb[4];
#pragma unroll
        for (int g2 = 0; g2 < 4; g2++) {
            float vs[2], vb[2];
#pragma unroll
            for (int u2 = 0; u2 < 2; u2++) {
                int u = g2 * 2 + u2;
                float d3 = fmaf(f2, fj[2][u], fmaf(f1, fj[1][u], f0 * fj[0][u]));
                float dh = fmaf(f5, fj[5][u], fmaf(f4, fj[4][u], f3 * fj[3][u]));
                float d6 = d3 + dh;
                vs[u2] = ex2f(fmaf(ESP, d3, -(hs + hsj[u])));
                vb[u2] = ex2f(fmaf(EBL, d6, -(hb + hbj[u])));
            }
            __nv_bfloat162 s2 = __floats2bfloat162_rn(vs[0], vs[1]);
            __nv_bfloat162 b2 = __floats2bfloat162_rn(vb[0], vb[1]);
            ps[g2] = *reinterpret_cast<uint32_t*>(&s2);
            pb[g2] = *reinterpret_cast<uint32_t*>(&b2);
        }
        int it_blk = (bi & 1) * 16 + it_local;
        size_t u4 = base4 + ((size_t)it_blk * 8 + js_blk) * 32 + lane;
        reinterpret_cast<uint4*>(g_Ksp)[u4] = make_uint4(ps[0], ps[1], ps[2], ps[3]);
        reinterpret_cast<uint4*>(g_Kbl)[u4] = make_uint4(pb[0], pb[1], pb[2], pb[3]);
    }
}

// ---------------- softmax + P-fragment writer / final output -----------------
// mode 0: q = unaries -> PF
// mode 1: q = unaries + g_red -> PF   (then zero g_red)
// mode 2: q = unaries + g_red -> out  (then zero g_red)
__global__ __launch_bounds__(128) void k_soft(const float* __restrict__ unaries,
                                              const float* __restrict__ Wsp,
                                              const float* __restrict__ Wbl,
                                              const float* __restrict__ Comp,
                                              float* __restrict__ out,
                                              int mode) {
    __shared__ float sW1[NC * NC], sW2[NC * NC];
    int tl = threadIdx.x;
    int j = blockIdx.x * 128 + tl;

    if (mode != 2 && tl < NC * NC) {
        int c = tl / NC, c2 = tl % NC;
        float s1 = 0.f, s2 = 0.f;
#pragma unroll
        for (int k = 0; k < NC; k++) {
            s1 += Comp[c * NC + k] * Wsp[k * NC + c2];
            s2 += Comp[c * NC + k] * Wbl[k * NC + c2];
        }
        sW1[tl] = -s1;
        sW2[tl] = -s2;
    }
    if (mode != 2) __syncthreads();

    float q[NC];
#pragma unroll
    for (int c = 0; c < NC; c++) q[c] = unaries[(size_t)c * NPT + j];
    if (mode) {
#pragma unroll
        for (int c = 0; c < NC; c++) {
            q[c] += g_red[c * NPT + j];
            g_red[c * NPT + j] = 0.f;      // restore zero invariant
        }
    }
    if (mode == 2) {
#pragma unroll
        for (int c = 0; c < NC; c++) out[(size_t)c * NPT + j] = q[c];
        return;
    }
    float p[NC];
    float m = q[0];
#pragma unroll
    for (int c = 1; c < NC; c++) m = fmaxf(m, q[c]);
    float s = 0.f;
#pragma unroll
    for (int c = 0; c < NC; c++) { p[c] = ex2f((q[c] - m) * LOG2E); s += p[c]; }
    float inv = __fdividef(1.f, s);
#pragma unroll
    for (int c = 0; c < NC; c++) p[c] *= inv;

    int T  = j >> 1, u = j & 1;
    int ks = T >> 3, tq = T & 3;
    int hik = ((T & 7) >= 4) ? 2 : 0;
#pragma unroll
    for (int c16 = 0; c16 < CP; c16++) {
        float v1 = 0.f, v2 = 0.f;
        if (c16 < NC) {
#pragma unroll
            for (int c = 0; c < NC; c++) {
                v1 = fmaf(sW1[c16 * NC + c], p[c], v1);
                v2 = fmaf(sW2[c16 * NC + c], p[c], v2);
            }
        }
        int lane = (c16 & 7) * 4 + tq;
        int reg  = ((c16 >= 8) ? 1 : 0) + hik;
        reinterpret_cast<__nv_bfloat16*>(&g_PF[0][ks][lane])[reg * 2 + u] =
            __float2bfloat16(v1);
        reinterpret_cast<__nv_bfloat16*>(&g_PF[1][ks][lane])[reg * 2 + u] =
            __float2bfloat16(v2);
    }
}

// ---------------- symmetric GEMM: barrier-free, movmatrix mirror (R13) -------
// CTA = pair (p<=q), 8 warps, 8 chunks; + L2 prefetch of next chunk's lines.
__global__ __launch_bounds__(256, 2) void k_gemm() {
    int t = threadIdx.x, w = t >> 5, lane = t & 31, g = lane >> 2, tq = lane & 3;

    int idx = blockIdx.x, p = 0;
    while (idx >= NBLK - p) { idx -= NBLK - p; p++; }
    int q = p + idx;
    bool diag = (p == q);

    const uint4* K1 = reinterpret_cast<const uint4*>(g_Ksp) + (size_t)blockIdx.x * BLKU4;
    const uint4* K2 = reinterpret_cast<const uint4*>(g_Kbl) + (size_t)blockIdx.x * BLKU4;

    // mirror A-fragments: constant across chunks (k16 groups w*2, w*2+1 of p)
    uint4 MA1[2], MA2[2];
#pragma unroll
    for (int s = 0; s < 2; s++) {
        MA1[s] = g_PF[0][p * 16 + w * 2 + s][lane];
        MA2[s] = g_PF[1][p * 16 + w * 2 + s][lane];
    }

    float facc[4][4] = {};

#pragma unroll 1
    for (int cs = 0; cs < 8; cs++) {
        // forward A-fragments for this chunk's 32 j (two k16 steps)
        int ks0 = q * 16 + cs * 2;
        uint4 A1a = g_PF[0][ks0][lane], A1b = g_PF[0][ks0 + 1][lane];
        uint4 A2a = g_PF[1][ks0][lane], A2b = g_PF[1][ks0 + 1][lane];

        // front-batched B loads: 8 contiguous 512B LDG.128 per warp
        uint4 B1[4], B2[4];
#pragma unroll
        for (int tt = 0; tt < 4; tt++) {
            size_t u4 = ((size_t)(w * 4 + tt) * 8 + cs) * 32 + lane;
            B1[tt] = K1[u4];
            B2[tt] = K2[u4];
        }
        // L2 prefetch of next chunk's lines (no regs, no ordering hazard)
        if (cs < 7) {
#pragma unroll
            for (int tt = 0; tt < 4; tt++) {
                size_t u4n = ((size_t)(w * 4 + tt) * 8 + cs + 1) * 32 + lane;
                pf_l2(K1 + u4n);
                pf_l2(K2 + u4n);
            }
        }

        // ---- forward: out[i in p-block] += P(q) . K ----
#pragma unroll
        for (int tt = 0; tt < 4; tt++) {
            mma16816(facc[tt], reinterpret_cast<const uint32_t*>(&A1a), B1[tt].x, B1[tt].y);
            mma16816(facc[tt], reinterpret_cast<const uint32_t*>(&A1b), B1[tt].z, B1[tt].w);
            mma16816(facc[tt], reinterpret_cast<const uint32_t*>(&A2a), B2[tt].x, B2[tt].y);
            mma16816(facc[tt], reinterpret_cast<const uint32_t*>(&A2b), B2[tt].z, B2[tt].w);
        }

        // ---- mirror: out[j in q-block] += P(p) . K^T  (movmatrix transpose) --
        if (!diag) {
            uint32_t T1[4][4], T2[4][4];
#pragma unroll
            for (int tt = 0; tt < 4; tt++) {
                const uint32_t* b1 = reinterpret_cast<const uint32_t*>(&B1[tt]);
                const uint32_t* b2 = reinterpret_cast<const uint32_t*>(&B2[tt]);
#pragma unroll
                for (int jo = 0; jo < 4; jo++) {
                    T1[tt][jo] = movm(b1[jo]);
                    T2[tt][jo] = movm(b2[jo]);
                }
            }
#pragma unroll
            for (int jo = 0; jo < 4; jo++) {
                float macc[4] = {0.f, 0.f, 0.f, 0.f};
                mma16816(macc, reinterpret_cast<const uint32_t*>(&MA1[0]), T1[0][jo], T1[1][jo]);
                mma16816(macc, reinterpret_cast<const uint32_t*>(&MA1[1]), T1[2][jo], T1[3][jo]);
                mma16816(macc, reinterpret_cast<const uint32_t*>(&MA2[0]), T2[0][jo], T2[1][jo]);
                mma16816(macc, reinterpret_cast<const uint32_t*>(&MA2[1]), T2[2][jo], T2[3][jo]);
                int j = q * 256 + cs * 32 + jo * 8 + tq * 2;
                redg2(&g_red[g * NPT + j], macc[0], macc[1]);
                if (g < NC - 8)
                    redg2(&g_red[(g + 8) * NPT + j], macc[2], macc[3]);
            }
        }
    }

    // ---- forward epilogue ----
#pragma unroll
    for (int tt = 0; tt < 4; tt++) {
        int i = p * 256 + (w * 4 + tt) * 8 + tq * 2;
        redg2(&g_red[g * NPT + i], facc[tt][0], facc[tt][1]);
        if (g < NC - 8)
            redg2(&g_red[(g + 8) * NPT + i], facc[tt][2], facc[tt][3]);
    }
}

// ---------------- launch ------------------------------------------------------
extern "C" void kernel_launch(void* const* d_in, const int* in_sizes, int n_in,
                              void* d_out, int out_size) {
    const float* unaries = (const float*)d_in[0];
    const float* feat    = (const float*)d_in[1];
    const float* Wsp     = (const float*)d_in[2];
    const float* Wbl     = (const float*)d_in[3];
    const float* Comp    = (const float*)d_in[4];
    float* out = (float*)d_out;

    k_nop<<<1, 32>>>();                                           // 0 (ncu shim)
    k_pairs<<<dim3(64, 64), 256>>>(feat);                         // 1
    k_soft<<<NPT / 128, 128>>>(unaries, Wsp, Wbl, Comp, out, 0);  // 2
    for (int it = 0; it < 5; it++) {
        k_gemm<<<NPAIR, 256>>>();                                 // 3,5,7,9,11 (5 = iter1)
        k_soft<<<NPT / 128, 128>>>(unaries, Wsp, Wbl, Comp, out,
                                   (it == 4) ? 2 : 1);            // 4,6,8,10,12
    }
}